// round 2
// baseline (speedup 1.0000x reference)
#include <cuda_runtime.h>

#define BB    8
#define NPTS  4096
#define KNN   20
#define TOTPTS (BB*NPTS)

// ---------------- static device scratch (sanctioned workaround) ----------------
static __device__ float g_h  [TOTPTS*64];   // features after conv1+conv2, (B,N,64)
static __device__ float g_nh [TOTPTS];      // ||h||^2
static __device__ float g_nx [TOTPTS];      // ||x||^2
static __device__ int   g_idx1[TOTPTS*KNN];
static __device__ int   g_idx2[TOTPTS*KNN];
static __device__ float g_a  [TOTPTS*64];   // (Wc-Wd)@h
static __device__ float g_u  [TOTPTS*64];   // Wd@h
static __device__ float g_hdg[TOTPTS*64];   // after dg branch max
static __device__ float g_p2 [TOTPTS*64];   // sn-branch per-point MLP output
static __device__ float g_hsn[TOTPTS*64];   // after sn gather-max (then conv3 in-place)
static __device__ float g_h4 [TOTPTS*128];  // after conv4

__device__ __forceinline__ float lrelu(float v){ return fmaxf(v, 0.01f*v); }

// pointer selectors (avoid host-side symbol lookups)
__device__ __forceinline__ const float* pconv_in(int sel){
    switch(sel){ case 0: return g_h; case 1: return g_hdg; case 2: return g_p2;
                 case 3: return g_hsn; default: return g_hsn; }
}
__device__ __forceinline__ float* pconv_out(int sel){
    switch(sel){ case 0: return g_h; case 1: return g_p2; case 2: return g_p2;
                 case 3: return g_hsn; default: return g_h4; }
}

// ---------------- conv1: x(B,N,3) -> g_h (64ch), one thread per (point,channel) ----------------
__global__ void k_conv1(const float* __restrict__ x, const float* __restrict__ w,
                        const float* __restrict__ g, const float* __restrict__ b)
{
    __shared__ float sw[192], sg[64], sb[64];
    int t = threadIdx.x;
    if (t < 192) sw[t] = w[t];
    if (t < 64){ sg[t] = g[t]; sb[t] = b[t]; }
    __syncthreads();
    int lp = t >> 6, c = t & 63;
    int p  = blockIdx.x*4 + lp;
    float x0 = x[p*3+0], x1 = x[p*3+1], x2 = x[p*3+2];
    float v = sw[c*3+0]*x0 + sw[c*3+1]*x1 + sw[c*3+2]*x2;
    g_h[p*64+c] = lrelu(v*sg[c] + sb[c]);
}

// ---------------- generic pointwise conv 64 -> COUT with BN+LReLU ----------------
template<int COUT>
__global__ void k_pconv(int sel, const float* __restrict__ w,
                        const float* __restrict__ g, const float* __restrict__ b)
{
    const int PPB = 256/COUT;
    __shared__ float wt[64*COUT];      // transposed: wt[k*COUT+c] = w[c*64+k]
    __shared__ float hs[PPB][64];
    __shared__ float sg[COUT], sb[COUT];
    const float* in  = pconv_in(sel);
    float*       out = pconv_out(sel);
    int t = threadIdx.x;
    for (int i = t; i < 64*COUT; i += 256){ int c = i>>6, k = i&63; wt[k*COUT+c] = w[i]; }
    for (int i = t; i < COUT;    i += 256){ sg[i] = g[i]; sb[i] = b[i]; }
    int lp = t / COUT, c = t % COUT;
    int p  = blockIdx.x*PPB + lp;
    if (c < 64) hs[lp][c] = in[p*64+c];
    __syncthreads();
    float wr[64];
    #pragma unroll
    for (int k = 0; k < 64; k++) wr[k] = wt[k*COUT+c];
    float s = 0.f;
    #pragma unroll
    for (int k = 0; k < 64; k++) s += wr[k]*hs[lp][k];
    out[p*COUT+c] = lrelu(s*sg[c] + sb[c]);
}

// ---------------- squared norms of h (after conv2) and of coords ----------------
__global__ void k_norms(const float* __restrict__ x)
{
    int p = blockIdx.x*256 + threadIdx.x;
    const float* hp = &g_h[p*64];
    float s = 0.f;
    #pragma unroll
    for (int k = 0; k < 64; k++){ float v = hp[k]; s += v*v; }
    g_nh[p] = s;
    float x0 = x[p*3], x1 = x[p*3+1], x2 = x[p*3+2];
    g_nx[p] = x0*x0 + x1*x1 + x2*x2;
}

// ---------------- pair matrix for one batch: pair[n][m] = 2*dot - nn[n] - nn[m] ----------------
template<int C>
__global__ void k_pair(int b, const float* __restrict__ x, float* __restrict__ pair)
{
    __shared__ float at[C][68];
    __shared__ float bt[C][68];
    const float* A;
    const float* nn;
    if (C == 64){ A = g_h + (size_t)b*NPTS*64; nn = g_nh + b*NPTS; }
    else        { A = x   + (size_t)b*NPTS*3;  nn = g_nx + b*NPTS; }
    int t  = threadIdx.x;
    int r0 = blockIdx.y*64, c0 = blockIdx.x*64;
    for (int i = t; i < 64*C; i += 256){ int r = i/C, c = i%C; at[c][r] = A[(r0+r)*C + c]; }
    for (int i = t; i < 64*C; i += 256){ int m = i/C, c = i%C; bt[c][m] = A[(c0+m)*C + c]; }
    __syncthreads();
    int tr = (t>>4)<<2, tc = (t&15)<<2;
    float acc[4][4] = {{0.f,0.f,0.f,0.f},{0.f,0.f,0.f,0.f},{0.f,0.f,0.f,0.f},{0.f,0.f,0.f,0.f}};
    #pragma unroll
    for (int c = 0; c < C; c++){
        float4 av = *(const float4*)&at[c][tr];
        float4 bv = *(const float4*)&bt[c][tc];
        acc[0][0] += av.x*bv.x; acc[0][1] += av.x*bv.y; acc[0][2] += av.x*bv.z; acc[0][3] += av.x*bv.w;
        acc[1][0] += av.y*bv.x; acc[1][1] += av.y*bv.y; acc[1][2] += av.y*bv.z; acc[1][3] += av.y*bv.w;
        acc[2][0] += av.z*bv.x; acc[2][1] += av.z*bv.y; acc[2][2] += av.z*bv.z; acc[2][3] += av.z*bv.w;
        acc[3][0] += av.w*bv.x; acc[3][1] += av.w*bv.y; acc[3][2] += av.w*bv.z; acc[3][3] += av.w*bv.w;
    }
    float cn[4];
    #pragma unroll
    for (int j = 0; j < 4; j++) cn[j] = nn[c0+tc+j];
    #pragma unroll
    for (int i = 0; i < 4; i++){
        float rn = nn[r0+tr+i];
        float4 o;
        o.x = 2.f*acc[i][0] - rn - cn[0];
        o.y = 2.f*acc[i][1] - rn - cn[1];
        o.z = 2.f*acc[i][2] - rn - cn[2];
        o.w = 2.f*acc[i][3] - rn - cn[3];
        *(float4*)&pair[(size_t)(r0+tr+i)*NPTS + c0 + tc] = o;
    }
}

// ---------------- top-20 per row (max value, ties -> smaller index, like jax top_k) ----------------
__global__ void k_topk(int b, int which, const float* __restrict__ pair)
{
    __shared__ float sv[NPTS];
    __shared__ unsigned long long wb[8];
    int t   = threadIdx.x;
    int row = blockIdx.x;
    const float* pr = &pair[(size_t)row*NPTS];
    for (int i = t; i < NPTS; i += 256) sv[i] = pr[i];
    __syncthreads();
    int* out = (which ? g_idx2 : g_idx1) + ((size_t)b*NPTS + row)*KNN;
    for (int it = 0; it < KNN; it++){
        unsigned long long best = 0ull;
        for (int i = t; i < NPTS; i += 256){
            unsigned u = __float_as_uint(sv[i]);
            u = (u & 0x80000000u) ? ~u : (u | 0x80000000u);
            unsigned long long key = ((unsigned long long)u << 32) | (unsigned)(NPTS-1-i);
            if (key > best) best = key;
        }
        #pragma unroll
        for (int o = 16; o; o >>= 1){
            unsigned long long other = __shfl_down_sync(0xffffffffu, best, o);
            if (other > best) best = other;
        }
        if ((t & 31) == 0) wb[t>>5] = best;
        __syncthreads();
        if (t == 0){
            unsigned long long bb = wb[0];
            for (int w = 1; w < 8; w++) if (wb[w] > bb) bb = wb[w];
            int idx = NPTS-1 - (int)(bb & 0xFFFFFFFFu);
            out[it] = idx;
            sv[idx] = -3.4e38f;
        }
        __syncthreads();
    }
}

// ---------------- dg precompute: a = (Wc-Wd)@h, u = Wd@h ----------------
__global__ void k_dgpre(const float* __restrict__ wdg1)
{
    __shared__ float wct[64*64], wdt[64*64];   // transposed [k][c]
    __shared__ float hs[4][64];
    int t = threadIdx.x;
    for (int i = t; i < 4096; i += 256){
        int c = i>>6, k = i&63;
        float wc = wdg1[c*128 + k], wd = wdg1[c*128 + 64 + k];
        wdt[k*64+c] = wd;
        wct[k*64+c] = wc - wd;
    }
    int lp = t>>6, c = t&63;
    int p  = blockIdx.x*4 + lp;
    hs[lp][c] = g_h[p*64+c];
    __syncthreads();
    float wa[64], wu[64];
    #pragma unroll
    for (int k = 0; k < 64; k++){ wa[k] = wct[k*64+c]; wu[k] = wdt[k*64+c]; }
    float sa = 0.f, su = 0.f;
    #pragma unroll
    for (int k = 0; k < 64; k++){ float h = hs[lp][k]; sa += wa[k]*h; su += wu[k]*h; }
    g_a[p*64+c] = sa;
    g_u[p*64+c] = su;
}

// ---------------- dg edge conv: per edge t1 = lrelu(bn(a_n + u_m)); t2 = dg2 GEMV; max over k ----------------
__global__ void k_dgedge(const float* __restrict__ w2,
                         const float* __restrict__ g1v, const float* __restrict__ b1v,
                         const float* __restrict__ g2v, const float* __restrict__ b2v)
{
    __shared__ float wt[4096];                 // transposed [k][c]
    __shared__ float t1s[4][64];
    __shared__ float sg1[64], sb1[64], sg2[64], sb2[64];
    int t = threadIdx.x;
    for (int i = t; i < 4096; i += 256){ int c = i>>6, k = i&63; wt[k*64+c] = w2[i]; }
    if (t < 64){ sg1[t] = g1v[t]; sb1[t] = b1v[t]; sg2[t] = g2v[t]; sb2[t] = b2v[t]; }
    __syncthreads();
    int lp = t>>6, c = t&63;
    int p    = blockIdx.x*4 + lp;
    int base = (p >> 12) * NPTS;               // batch base
    float wr[64];
    #pragma unroll
    for (int k = 0; k < 64; k++) wr[k] = wt[k*64+c];
    float ac = g_a[p*64+c];
    float G1 = sg1[c], B1 = sb1[c], G2 = sg2[c], B2 = sb2[c];
    float mx = -3.4e38f;
    const int* ip = &g_idx1[p*KNN];
    for (int j = 0; j < KNN; j++){
        int m = ip[j];
        float v = (ac + g_u[(base+m)*64 + c]) * G1 + B1;
        t1s[lp][c] = lrelu(v);
        __syncthreads();
        float s = 0.f;
        #pragma unroll
        for (int k = 0; k < 64; k++) s += wr[k]*t1s[lp][k];
        s = lrelu(s*G2 + B2);
        mx = fmaxf(mx, s);
        __syncthreads();
    }
    g_hdg[p*64+c] = mx;
}

// ---------------- sn branch: gather-max of per-point MLP output ----------------
__global__ void k_snmax()
{
    int t = threadIdx.x;
    int lp = t>>6, c = t&63;
    int p    = blockIdx.x*4 + lp;
    int base = (p >> 12) * NPTS;
    const int* ip = &g_idx2[p*KNN];
    float mx = -3.4e38f;
    for (int j = 0; j < KNN; j++){
        int m = ip[j];
        mx = fmaxf(mx, g_p2[(base+m)*64 + c]);
    }
    g_hsn[p*64+c] = mx;
}

// ---------------- conv5 GEMM: out[b,co,n] = lrelu(bn(w5[co,:] . h4[b,n,:])) ----------------
__global__ void k_conv5(const float* __restrict__ w5, const float* __restrict__ g5,
                        const float* __restrict__ b5, float* __restrict__ out)
{
    __shared__ float wt[64][68];
    __shared__ float ht[64][68];
    int t   = threadIdx.x;
    int co0 = blockIdx.y*64;
    int pt0 = blockIdx.x*64;
    int tr = (t>>4)<<2, tc = (t&15)<<2;
    float acc[4][4] = {{0.f,0.f,0.f,0.f},{0.f,0.f,0.f,0.f},{0.f,0.f,0.f,0.f},{0.f,0.f,0.f,0.f}};
    for (int kc = 0; kc < 2; kc++){
        __syncthreads();
        for (int i = t; i < 4096; i += 256){ int c = i>>6, k = i&63; wt[k][c] = w5[(co0+c)*128 + kc*64 + k]; }
        for (int i = t; i < 4096; i += 256){ int q = i>>6, k = i&63; ht[k][q] = g_h4[(size_t)(pt0+q)*128 + kc*64 + k]; }
        __syncthreads();
        #pragma unroll
        for (int k = 0; k < 64; k++){
            float4 wv = *(const float4*)&wt[k][tr];
            float4 hv = *(const float4*)&ht[k][tc];
            acc[0][0] += wv.x*hv.x; acc[0][1] += wv.x*hv.y; acc[0][2] += wv.x*hv.z; acc[0][3] += wv.x*hv.w;
            acc[1][0] += wv.y*hv.x; acc[1][1] += wv.y*hv.y; acc[1][2] += wv.y*hv.z; acc[1][3] += wv.y*hv.w;
            acc[2][0] += wv.z*hv.x; acc[2][1] += wv.z*hv.y; acc[2][2] += wv.z*hv.z; acc[2][3] += wv.z*hv.w;
            acc[3][0] += wv.w*hv.x; acc[3][1] += wv.w*hv.y; acc[3][2] += wv.w*hv.z; acc[3][3] += wv.w*hv.w;
        }
    }
    int bI = pt0 >> 12;
    int n0 = (pt0 + tc) & (NPTS-1);
    #pragma unroll
    for (int i = 0; i < 4; i++){
        int co = co0 + tr + i;
        float G = g5[co], Bv = b5[co];
        float4 o;
        o.x = lrelu(acc[i][0]*G + Bv);
        o.y = lrelu(acc[i][1]*G + Bv);
        o.z = lrelu(acc[i][2]*G + Bv);
        o.w = lrelu(acc[i][3]*G + Bv);
        *(float4*)&out[((size_t)bI*512 + co)*NPTS + n0] = o;
    }
}

// ---------------- launch ----------------
extern "C" void kernel_launch(void* const* d_in, const int* in_sizes, int n_in,
                              void* d_out, int out_size)
{
    const float* x    = (const float*)d_in[0];
    const float* w1   = (const float*)d_in[1];
    const float* g1   = (const float*)d_in[2];
    const float* b1   = (const float*)d_in[3];
    const float* w2   = (const float*)d_in[4];
    const float* g2   = (const float*)d_in[5];
    const float* b2   = (const float*)d_in[6];
    const float* wdg1 = (const float*)d_in[7];
    const float* gdg1 = (const float*)d_in[8];
    const float* bdg1 = (const float*)d_in[9];
    const float* wdg2 = (const float*)d_in[10];
    const float* gdg2 = (const float*)d_in[11];
    const float* bdg2 = (const float*)d_in[12];
    const float* wsn1 = (const float*)d_in[13];
    const float* gsn1 = (const float*)d_in[14];
    const float* bsn1 = (const float*)d_in[15];
    const float* wsn2 = (const float*)d_in[16];
    const float* gsn2 = (const float*)d_in[17];
    const float* bsn2 = (const float*)d_in[18];
    const float* w3   = (const float*)d_in[19];
    const float* g3   = (const float*)d_in[20];
    const float* b3   = (const float*)d_in[21];
    const float* w4   = (const float*)d_in[22];
    const float* g4   = (const float*)d_in[23];
    const float* b4   = (const float*)d_in[24];
    const float* w5   = (const float*)d_in[25];
    const float* g5   = (const float*)d_in[26];
    const float* b5   = (const float*)d_in[27];

    float* out  = (float*)d_out;
    // d_out (8*512*4096 floats) doubles as the 4096x4096 pair-matrix scratch
    // during the KNN phase; conv5 overwrites it at the very end.
    float* pair = (float*)d_out;

    // conv1 + conv2 (in-place) + norms
    k_conv1   <<<TOTPTS/4, 256>>>(x, w1, g1, b1);
    k_pconv<64><<<TOTPTS/4, 256>>>(0, w2, g2, b2);
    k_norms   <<<TOTPTS/256, 256>>>(x);

    // KNN on 64-d features -> idx1
    for (int b = 0; b < BB; b++){
        k_pair<64><<<dim3(64,64), 256>>>(b, x, pair);
        k_topk    <<<NPTS, 256>>>(b, 0, pair);
    }
    // KNN on 3-d coords -> idx2
    for (int b = 0; b < BB; b++){
        k_pair<3><<<dim3(64,64), 256>>>(b, x, pair);
        k_topk   <<<NPTS, 256>>>(b, 1, pair);
    }

    // dg branch
    k_dgpre <<<TOTPTS/4, 256>>>(wdg1);
    k_dgedge<<<TOTPTS/4, 256>>>(wdg2, gdg1, bdg1, gdg2, bdg2);

    // sn branch: per-point MLP then gather-max
    k_pconv<64><<<TOTPTS/4, 256>>>(1, wsn1, gsn1, bsn1);
    k_pconv<64><<<TOTPTS/4, 256>>>(2, wsn2, gsn2, bsn2);
    k_snmax    <<<TOTPTS/4, 256>>>();

    // head
    k_pconv<64> <<<TOTPTS/4, 256>>>(3, w3, g3, b3);
    k_pconv<128><<<TOTPTS/2, 256>>>(4, w4, g4, b4);
    k_conv5     <<<dim3(TOTPTS/64, 512/64), 256>>>(w5, g5, b5, out);
}